// round 14
// baseline (speedup 1.0000x reference)
#include <cuda_runtime.h>
#include <cuda_bf16.h>

#define NN   50000
#define EE   800000
#define ET   (EE + NN)
#define DIN  128
#define HIDN 64
#define OUTC 32
#define NB   64
#define NHEAD 4

#define NEG_SLOPE 0.2f
#define BN_EPS 1e-5f

// ---------------- scratch (zero-initialized at module load; k_final restores) -
__device__ float2 d_xl1p[NN * 32];     // paired: [n][c] = (col c, col c+32)
__device__ float d_es1[NN * NHEAD];
__device__ float d_ed1[NN * NHEAD];
__device__ float d_h1[NN * HIDN];
__device__ float d_stats1[2 * HIDN];   // reset by k_final

__device__ float d_xl2[NN * OUTC];
__device__ float d_es2[NN];
__device__ float d_ed2[NN];
__device__ float d_h2[NN * OUTC];
__device__ float d_stats2[2 * OUTC];   // reset by k_final

__device__ float d_gsum[NB * OUTC];    // reset by k_final
__device__ float d_gmax[NB * OUTC];    // reset by k_final (to -inf)
__device__ float d_gcnt[NB];           // reset by k_final

// CSR (by dst)
__device__ int d_deg[NN];              // reset by k_alloc
__device__ int d_off[NN];
__device__ int d_end[NN];
__device__ int d_cursor[NN];
__device__ int d_csrc[ET];
__device__ int d_total;                // reset by k_final

__device__ __forceinline__ float NEG_INF() { return __int_as_float(0xff800000); }

__device__ __forceinline__ void atomicMaxF(float* addr, float v) {
    if (v >= 0.0f) atomicMax((int*)addr, __float_as_int(v));
    else           atomicMin((unsigned int*)addr, __float_as_uint(v));
}

__device__ __forceinline__ float lrelu(float e) { return e > 0.f ? e : NEG_SLOPE * e; }

typedef unsigned long long ull;
__device__ __forceinline__ ull pack2dup(float x) {
    ull r;
    asm("mov.b64 %0, {%1,%2};" : "=l"(r) : "f"(x), "f"(x));
    return r;
}
__device__ __forceinline__ ull ffma2(ull a, ull b, ull c) {
    ull d;
    asm("fma.rn.f32x2 %0, %1, %2, %3;" : "=l"(d) : "l"(a), "l"(b), "l"(c));
    return d;
}
__device__ __forceinline__ float2 unpack2(ull v) {
    float2 f;
    asm("mov.b64 {%0,%1}, %2;" : "=f"(f.x), "=f"(f.y) : "l"(v));
    return f;
}

// ---------------- CSR build ---------------------------------------------------
__global__ __launch_bounds__(256) void k_deg_count(const int* __restrict__ ei) {
    int i = blockIdx.x * blockDim.x + threadIdx.x;
    if (i >= EE / 4) return;
    int4 d4 = ((const int4*)(ei + EE))[i];
    atomicAdd(&d_deg[d4.x], 1);
    atomicAdd(&d_deg[d4.y], 1);
    atomicAdd(&d_deg[d4.z], 1);
    atomicAdd(&d_deg[d4.w], 1);
}

// Parallel segment allocation: per-block scan + one atomicAdd for base.
__global__ __launch_bounds__(256) void k_alloc() {
    __shared__ int wsum[8];
    __shared__ int sbase;
    int tid = threadIdx.x, lane = tid & 31, w = tid >> 5;
    int i = blockIdx.x * 256 + tid;
    int cnt = (i < NN) ? d_deg[i] + 1 : 0;      // +1 self loop
    int sc = cnt;
    #pragma unroll
    for (int o = 1; o < 32; o <<= 1) {
        int v = __shfl_up_sync(0xffffffffu, sc, o);
        if (lane >= o) sc += v;
    }
    if (lane == 31) wsum[w] = sc;
    __syncthreads();
    if (w == 0) {
        int s = (lane < 8) ? wsum[lane] : 0;
        #pragma unroll
        for (int o = 1; o < 8; o <<= 1) {
            int v = __shfl_up_sync(0xffffffffu, s, o);
            if (lane >= o) s += v;
        }
        if (lane < 8) wsum[lane] = s;
        if (lane == 7) sbase = atomicAdd(&d_total, s);
    }
    __syncthreads();
    if (i < NN) {
        int base = sbase + (w > 0 ? wsum[w - 1] : 0) + sc - cnt;
        d_off[i] = base;
        d_cursor[i] = base;
        d_end[i] = base + cnt;
        d_deg[i] = 0;                            // restore for next replay
    }
}

__global__ __launch_bounds__(256) void k_fill(const int* __restrict__ ei) {
    int i = blockIdx.x * blockDim.x + threadIdx.x;
    if (i < EE / 4) {
        int4 s4 = ((const int4*)ei)[i];
        int4 t4 = ((const int4*)(ei + EE))[i];
        int p0 = atomicAdd(&d_cursor[t4.x], 1); d_csrc[p0] = s4.x;
        int p1 = atomicAdd(&d_cursor[t4.y], 1); d_csrc[p1] = s4.y;
        int p2 = atomicAdd(&d_cursor[t4.z], 1); d_csrc[p2] = s4.z;
        int p3 = atomicAdd(&d_cursor[t4.w], 1); d_csrc[p3] = s4.w;
    } else {
        int base = (i - EE / 4) * 4;
        #pragma unroll
        for (int r = 0; r < 4; r++) {
            int node = base + r;
            if (node < NN) {
                int pos = atomicAdd(&d_cursor[node], 1);
                d_csrc[pos] = node;
            }
        }
    }
}

// ---------------- GEMM1 + fused prep1 (64-row tiles, one per block) ----------
#define XPAD 68
#define NTILE1 ((NN + 63) / 64)
__global__ __launch_bounds__(256) void k_gemm1(const float* __restrict__ x,
                                               const float* __restrict__ W1,
                                               const float* __restrict__ a_src,
                                               const float* __restrict__ a_dst) {
    __shared__ float Wsm[DIN * HIDN];                 // 32 KB
    __shared__ __align__(16) float xs[64 * XPAD];     // 17.4 KB
    __shared__ float sa_s[HIDN], sd_s[HIDN];
    int tid = threadIdx.x, lane = tid & 31, w = tid >> 5;
    for (int i = tid; i < DIN * HIDN; i += 256) Wsm[i] = W1[i];
    if (tid < HIDN) { sa_s[tid] = a_src[tid]; sd_s[tid] = a_dst[tid]; }
    __syncthreads();
    int cp = lane;
    int r0 = w * 8;
    float wa0 = sa_s[cp], wa1 = sa_s[cp + 32];
    float wd0 = sd_s[cp], wd1 = sd_s[cp + 32];
    int h0 = cp >> 4;

    for (int tile = blockIdx.x; tile < NTILE1; tile += gridDim.x) {
        int row0 = tile * 64;
        ull acc[4][2] = {{0ull,0ull},{0ull,0ull},{0ull,0ull},{0ull,0ull}};
        #pragma unroll
        for (int half = 0; half < 2; half++) {
            __syncthreads();
            for (int i = tid; i < 64 * 64; i += 256) {
                int rr = i >> 6, k = i & 63;
                int row = row0 + rr;
                xs[k * XPAD + rr] = (row < NN) ? x[row * DIN + half * 64 + k] : 0.f;
            }
            __syncthreads();
            int kw = half * 64;
            #pragma unroll 4
            for (int k = 0; k < 64; k++) {
                const float* xk = xs + k * XPAD + r0;
                ulonglong2 A = *(const ulonglong2*)xk;
                ulonglong2 B = *(const ulonglong2*)(xk + 4);
                ull w0d = pack2dup(Wsm[(kw + k) * HIDN + cp]);
                ull w1d = pack2dup(Wsm[(kw + k) * HIDN + cp + 32]);
                acc[0][0] = ffma2(A.x, w0d, acc[0][0]);
                acc[0][1] = ffma2(A.x, w1d, acc[0][1]);
                acc[1][0] = ffma2(A.y, w0d, acc[1][0]);
                acc[1][1] = ffma2(A.y, w1d, acc[1][1]);
                acc[2][0] = ffma2(B.x, w0d, acc[2][0]);
                acc[2][1] = ffma2(B.x, w1d, acc[2][1]);
                acc[3][0] = ffma2(B.y, w0d, acc[3][0]);
                acc[3][1] = ffma2(B.y, w1d, acc[3][1]);
            }
        }
        #pragma unroll
        for (int rp = 0; rp < 4; rp++) {
            float2 o0 = unpack2(acc[rp][0]);
            float2 o1 = unpack2(acc[rp][1]);
            #pragma unroll
            for (int half = 0; half < 2; half++) {
                int row = row0 + r0 + 2 * rp + half;
                if (row >= NN) continue;
                float vx = half ? o0.y : o0.x;
                float vy = half ? o1.y : o1.x;
                d_xl1p[row * 32 + cp] = make_float2(vx, vy);
                float sax = vx * wa0, say = vy * wa1;
                float sdx = vx * wd0, sdy = vy * wd1;
                #pragma unroll
                for (int o = 8; o > 0; o >>= 1) {
                    sax += __shfl_xor_sync(0xffffffffu, sax, o);
                    say += __shfl_xor_sync(0xffffffffu, say, o);
                    sdx += __shfl_xor_sync(0xffffffffu, sdx, o);
                    sdy += __shfl_xor_sync(0xffffffffu, sdy, o);
                }
                if ((lane & 15) == 0) {
                    d_es1[row * 4 + h0]     = sax;
                    d_es1[row * 4 + h0 + 2] = say;
                    d_ed1[row * 4 + h0]     = sdx;
                    d_ed1[row * 4 + h0 + 2] = sdy;
                }
            }
        }
    }
}

// ---------------- layer-1 GAT + fused BN1 stats ------------------------------
__global__ __launch_bounds__(256) void k_gat1() {
    __shared__ float s_sum[HIDN], s_sq[HIDN];
    __shared__ float4 ps[8][32];   // {p0,p2,p1,p3}
    __shared__ int    se[8][32];
    int tid = threadIdx.x;
    int lane = tid & 31, w = tid >> 5;
    if (tid < HIDN) { s_sum[tid] = 0.f; s_sq[tid] = 0.f; }
    __syncthreads();
    int h0 = lane >> 4;
    const float2* pb = (const float2*)&ps[w][0];
    for (int n = blockIdx.x * 8 + w; n < NN; n += gridDim.x * 8) {
        int start = d_off[n], end = d_end[n];
        float4 ed = *(const float4*)&d_ed1[n * 4];
        float acc0 = 0.f, acc1 = 0.f;
        float s0 = 0.f, s1 = 0.f, s2 = 0.f, s3 = 0.f;
        for (int j0 = start; j0 < end; j0 += 32) {
            int j = j0 + lane;
            int cnt = min(32, end - j0);
            int s = 0;
            float p0 = 0.f, p1 = 0.f, p2 = 0.f, p3 = 0.f;
            if (j < end) {
                s = d_csrc[j];
                float4 es = *(const float4*)&d_es1[s * 4];
                p0 = __expf(lrelu(es.x + ed.x));
                p1 = __expf(lrelu(es.y + ed.y));
                p2 = __expf(lrelu(es.z + ed.z));
                p3 = __expf(lrelu(es.w + ed.w));
            }
            s0 += p0; s1 += p1; s2 += p2; s3 += p3;
            ps[w][lane] = make_float4(p0, p2, p1, p3);
            se[w][lane] = s;
            __syncwarp();
            int t = 0;
            for (; t + 4 <= cnt; t += 4) {
                int ssb[4]; float2 pq[4]; float2 f[4];
                #pragma unroll
                for (int u = 0; u < 4; u++) {
                    ssb[u] = se[w][t + u];
                    pq[u]  = pb[2 * (t + u) + h0];
                }
                #pragma unroll
                for (int u = 0; u < 4; u++) f[u] = d_xl1p[ssb[u] * 32 + lane];
                #pragma unroll
                for (int u = 0; u < 4; u++) {
                    acc0 += pq[u].x * f[u].x;
                    acc1 += pq[u].y * f[u].y;
                }
            }
            for (; t < cnt; t++) {
                int ss = se[w][t];
                float2 pq = pb[2 * t + h0];
                float2 f = d_xl1p[ss * 32 + lane];
                acc0 += pq.x * f.x;
                acc1 += pq.y * f.y;
            }
            __syncwarp();
        }
        #pragma unroll
        for (int o = 16; o > 0; o >>= 1) {
            s0 += __shfl_xor_sync(0xffffffffu, s0, o);
            s1 += __shfl_xor_sync(0xffffffffu, s1, o);
            s2 += __shfl_xor_sync(0xffffffffu, s2, o);
            s3 += __shfl_xor_sync(0xffffffffu, s3, o);
        }
        float sA = h0 ? s1 : s0;
        float sB = h0 ? s3 : s2;
        float v0 = acc0 / (sA + 1e-16f);
        float v1 = acc1 / (sB + 1e-16f);
        d_h1[n * HIDN + lane]      = v0;
        d_h1[n * HIDN + 32 + lane] = v1;
        atomicAdd(&s_sum[lane], v0);       atomicAdd(&s_sum[32 + lane], v1);
        atomicAdd(&s_sq[lane], v0 * v0);   atomicAdd(&s_sq[32 + lane], v1 * v1);
    }
    __syncthreads();
    if (tid < HIDN) {
        atomicAdd(&d_stats1[tid], s_sum[tid]);
        atomicAdd(&d_stats1[HIDN + tid], s_sq[tid]);
    }
}

// ---------------- GEMM2 (BN1 fused) + fused prep2, 16-row tiles --------------
__global__ __launch_bounds__(256) void k_gemm2(const float* __restrict__ W2,
                                               const float* __restrict__ g1,
                                               const float* __restrict__ be1,
                                               const float* __restrict__ a_src2,
                                               const float* __restrict__ a_dst2) {
    __shared__ float Ws[HIDN * OUTC];
    __shared__ float xs[16][HIDN];
    __shared__ float bnm[HIDN], bna[HIDN];
    int tid = threadIdx.x;
    for (int i = tid; i < HIDN * OUTC; i += 256) Ws[i] = W2[i];
    if (tid < HIDN) {
        float mu  = d_stats1[tid] * (1.0f / NN);
        float var = d_stats1[HIDN + tid] * (1.0f / NN) - mu * mu;
        float m = rsqrtf(var + BN_EPS) * g1[tid];
        bnm[tid] = m;
        bna[tid] = be1[tid] - mu * m;
    }
    int col = tid & 31;
    int r   = tid >> 5;
    float a2s = a_src2[col], a2d = a_dst2[col];
    for (int row0 = blockIdx.x * 16; row0 < NN; row0 += gridDim.x * 16) {
        __syncthreads();
        for (int i = tid; i < 16 * HIDN; i += 256) {
            int rr = i >> 6, k = i & 63;
            int row = row0 + rr;
            float hv = (row < NN) ? d_h1[row * HIDN + k] : 0.f;
            xs[rr][k] = fmaxf(fmaf(hv, bnm[k], bna[k]), 0.f);
        }
        __syncthreads();
        #pragma unroll
        for (int half = 0; half < 2; half++) {
            int rr = r + half * 8;
            int row = row0 + rr;
            if (row < NN) {
                float acc = 0.f;
                #pragma unroll
                for (int k = 0; k < HIDN; k++) acc = fmaf(xs[rr][k], Ws[k * OUTC + col], acc);
                d_xl2[row * OUTC + col] = acc;
                float es = acc * a2s, edv = acc * a2d;
                #pragma unroll
                for (int o = 16; o > 0; o >>= 1) {
                    es  += __shfl_xor_sync(0xffffffffu, es, o);
                    edv += __shfl_xor_sync(0xffffffffu, edv, o);
                }
                if (col == 0) { d_es2[row] = es; d_ed2[row] = edv; }
            }
        }
    }
}

// ---------------- layer-2 GAT + fused BN2 stats ------------------------------
__global__ __launch_bounds__(256) void k_gat2() {
    __shared__ float s_sum[OUTC], s_sq[OUTC];
    int tid = threadIdx.x;
    int lane = tid & 31, w = tid >> 5;
    if (tid < OUTC) { s_sum[tid] = 0.f; s_sq[tid] = 0.f; }
    __syncthreads();
    for (int n = blockIdx.x * 8 + w; n < NN; n += gridDim.x * 8) {
        int start = d_off[n], end = d_end[n];
        float ed = d_ed2[n];
        float acc = 0.f, psum = 0.f;
        for (int j0 = start; j0 < end; j0 += 32) {
            int j = j0 + lane;
            int cnt = min(32, end - j0);
            int s = 0;
            float p = 0.f;
            if (j < end) {
                s = d_csrc[j];
                p = __expf(lrelu(d_es2[s] + ed));
            }
            psum += p;
            int t = 0;
            for (; t + 4 <= cnt; t += 4) {
                int ssb[4]; float pp[4], f[4];
                #pragma unroll
                for (int u = 0; u < 4; u++) {
                    ssb[u] = __shfl_sync(0xffffffffu, s, t + u);
                    pp[u]  = __shfl_sync(0xffffffffu, p, t + u);
                }
                #pragma unroll
                for (int u = 0; u < 4; u++) f[u] = d_xl2[ssb[u] * OUTC + lane];
                #pragma unroll
                for (int u = 0; u < 4; u++) acc += pp[u] * f[u];
            }
            for (; t < cnt; t++) {
                int   ss = __shfl_sync(0xffffffffu, s, t);
                float pp = __shfl_sync(0xffffffffu, p, t);
                acc += pp * d_xl2[ss * OUTC + lane];
            }
        }
        #pragma unroll
        for (int o = 16; o > 0; o >>= 1)
            psum += __shfl_xor_sync(0xffffffffu, psum, o);
        float v = acc / (psum + 1e-16f);
        d_h2[n * OUTC + lane] = v;
        atomicAdd(&s_sum[lane], v);
        atomicAdd(&s_sq[lane], v * v);
    }
    __syncthreads();
    if (tid < OUTC) {
        atomicAdd(&d_stats2[tid], s_sum[tid]);
        atomicAdd(&d_stats2[OUTC + tid], s_sq[tid]);
    }
}

// ---------------- BN2 + node_emb + pooling (smem-accumulated) ----------------
#define PB_NODES 256
__global__ __launch_bounds__(256) void k_bn2_pool(const float* __restrict__ g2,
                                                  const float* __restrict__ be2,
                                                  const int* __restrict__ batch,
                                                  float* __restrict__ out) {
    __shared__ float lsum[NB * OUTC];
    __shared__ float lmax[NB * OUTC];
    __shared__ float lcnt[NB];
    int tid = threadIdx.x;
    for (int i = tid; i < NB * OUTC; i += 256) { lsum[i] = 0.f; lmax[i] = NEG_INF(); }
    if (tid < NB) lcnt[tid] = 0.f;
    int col = tid & 31;
    float mu  = d_stats2[col] * (1.0f / NN);
    float var = d_stats2[OUTC + col] * (1.0f / NN) - mu * mu;
    float m = rsqrtf(var + BN_EPS) * g2[col];
    float a = be2[col] - mu * m;
    int n0 = blockIdx.x * PB_NODES;
    __syncthreads();
    #pragma unroll 4
    for (int k = 0; k < PB_NODES * OUTC / 256; k++) {
        int idx = n0 * OUTC + k * 256 + tid;
        int node = idx >> 5;
        if (node < NN) {
            float v = fmaf(d_h2[idx], m, a);
            out[idx] = v;
            int b = batch[node];
            atomicAdd(&lsum[b * OUTC + col], v);
            atomicMaxF(&lmax[b * OUTC + col], v);
            if (col == 0) atomicAdd(&lcnt[b], 1.f);
        }
    }
    __syncthreads();
    int nlast = min(n0 + PB_NODES, NN) - 1;
    int bmin = batch[n0], bmax = batch[nlast];
    for (int j = tid; j < (bmax - bmin + 1) * OUTC; j += 256) {
        int b = bmin + (j >> 5), c = j & 31;
        float sv = lsum[b * OUTC + c];
        if (sv != 0.f) atomicAdd(&d_gsum[b * OUTC + c], sv);
        float mv = lmax[b * OUTC + c];
        if (mv > NEG_INF()) atomicMaxF(&d_gmax[b * OUTC + c], mv);
        if (c == 0) {
            float cv = lcnt[b];
            if (cv != 0.f) atomicAdd(&d_gcnt[b], cv);
        }
    }
}

// ---------------- final MLP + scratch restore --------------------------------
__global__ __launch_bounds__(256) void k_final(const float* __restrict__ fcW1,
                                               const float* __restrict__ fcb1,
                                               const float* __restrict__ fcW2,
                                               const float* __restrict__ fcb2,
                                               float* __restrict__ out) {
    __shared__ float g[NB * 2 * OUTC];
    __shared__ float t[NB * OUTC];
    int tid = threadIdx.x;
    for (int i = tid; i < NB * 2 * OUTC; i += 256) {
        int b = i >> 6, j = i & 63;
        float v;
        if (j < OUTC) {
            v = d_gsum[b * OUTC + j] / fmaxf(d_gcnt[b], 1.f);
        } else {
            v = d_gmax[b * OUTC + (j - OUTC)];
            if (v < -3e37f) v = 0.f;
        }
        g[i] = v;
    }
    __syncthreads();
    // restore accumulators for the next replay
    for (int i = tid; i < NB * OUTC; i += 256) { d_gsum[i] = 0.f; d_gmax[i] = NEG_INF(); }
    if (tid < NB) d_gcnt[tid] = 0.f;
    if (tid < 2 * HIDN) d_stats1[tid] = 0.f;
    if (tid < 2 * OUTC) d_stats2[tid] = 0.f;
    if (tid == 0) d_total = 0;
    // MLP
    for (int i = tid; i < NB * OUTC; i += 256) {
        int b = i >> 5, o = i & 31;
        float acc = fcb1[o];
        #pragma unroll
        for (int j = 0; j < 2 * OUTC; j++) acc = fmaf(g[b * 64 + j], fcW1[j * OUTC + o], acc);
        t[i] = fmaxf(acc, 0.f);
    }
    __syncthreads();
    for (int i = tid; i < NB * OUTC; i += 256) {
        int b = i >> 5, o = i & 31;
        float acc = fcb2[o];
        #pragma unroll
        for (int j = 0; j < OUTC; j++) acc = fmaf(t[b * OUTC + j], fcW2[j * OUTC + o], acc);
        out[NN * OUTC + i] = acc;
    }
}

// =============================================================================
extern "C" void kernel_launch(void* const* d_in, const int* in_sizes, int n_in,
                              void* d_out, int out_size) {
    const float* x      = (const float*)d_in[0];
    const int*   ei     = (const int*)  d_in[1];
    const int*   batch  = (const int*)  d_in[2];
    const float* W1     = (const float*)d_in[3];
    const float* a_src1 = (const float*)d_in[4];
    const float* a_dst1 = (const float*)d_in[5];
    const float* g1     = (const float*)d_in[7];
    const float* be1    = (const float*)d_in[8];
    const float* W2     = (const float*)d_in[9];
    const float* a_src2 = (const float*)d_in[10];
    const float* a_dst2 = (const float*)d_in[11];
    const float* g2     = (const float*)d_in[13];
    const float* be2    = (const float*)d_in[14];
    const float* fcW1   = (const float*)d_in[15];
    const float* fcb1   = (const float*)d_in[16];
    const float* fcW2   = (const float*)d_in[17];
    const float* fcb2   = (const float*)d_in[18];
    float* out = (float*)d_out;

    k_deg_count<<<(EE / 4 + 255) / 256, 256>>>(ei);
    k_alloc<<<(NN + 255) / 256, 256>>>();
    k_fill<<<((EE / 4 + (NN + 3) / 4) + 255) / 256, 256>>>(ei);
    k_gemm1<<<NTILE1, 256>>>(x, W1, a_src1, a_dst1);   // launch #4 (ncu slot), grid=782

    k_gat1<<<592, 256>>>();

    k_gemm2<<<592, 256>>>(W2, g1, be1, a_src2, a_dst2);
    k_gat2<<<592, 256>>>();
    k_bn2_pool<<<(NN + PB_NODES - 1) / PB_NODES, 256>>>(g2, be2, batch, out);

    k_final<<<1, 256>>>(fcW1, fcb1, fcW2, fcb2, out);
}

// round 15
// speedup vs baseline: 1.4351x; 1.4351x over previous
#include <cuda_runtime.h>
#include <cuda_bf16.h>

#define NN   50000
#define EE   800000
#define ET   (EE + NN)
#define DIN  128
#define HIDN 64
#define OUTC 32
#define NB   64
#define NHEAD 4

#define NEG_SLOPE 0.2f
#define BN_EPS 1e-5f

// ---------------- scratch (zero-initialized at module load; k_final restores) -
__device__ float2 d_xl1p[NN * 32];     // paired: [n][c] = (col c, col c+32)
__device__ float d_es1[NN * NHEAD];
__device__ float d_ed1[NN * NHEAD];
__device__ float d_h1[NN * HIDN];
__device__ float d_stats1[2 * HIDN];   // reset by k_final

__device__ float d_xl2[NN * OUTC];
__device__ float d_es2[NN];
__device__ float d_ed2[NN];
__device__ float d_h2[NN * OUTC];
__device__ float d_stats2[2 * OUTC];   // reset by k_final

__device__ float d_gsum[NB * OUTC];    // reset by k_final
__device__ float d_gmax[NB * OUTC];    // reset by k_final (to -inf)
__device__ float d_gcnt[NB];           // reset by k_final

// CSR (by dst)
__device__ int d_deg[NN];              // reset by k_alloc
__device__ int d_off[NN];
__device__ int d_end[NN];
__device__ int d_cursor[NN];
__device__ int d_csrc[ET];
__device__ int d_total;                // reset by k_final

__device__ __forceinline__ float NEG_INF() { return __int_as_float(0xff800000); }

__device__ __forceinline__ void atomicMaxF(float* addr, float v) {
    if (v >= 0.0f) atomicMax((int*)addr, __float_as_int(v));
    else           atomicMin((unsigned int*)addr, __float_as_uint(v));
}

__device__ __forceinline__ float lrelu(float e) { return e > 0.f ? e : NEG_SLOPE * e; }

typedef unsigned long long ull;
__device__ __forceinline__ ull pack2dup(float x) {
    ull r;
    asm("mov.b64 %0, {%1,%2};" : "=l"(r) : "f"(x), "f"(x));
    return r;
}
__device__ __forceinline__ ull ffma2(ull a, ull b, ull c) {
    ull d;
    asm("fma.rn.f32x2 %0, %1, %2, %3;" : "=l"(d) : "l"(a), "l"(b), "l"(c));
    return d;
}
__device__ __forceinline__ float2 unpack2(ull v) {
    float2 f;
    asm("mov.b64 {%0,%1}, %2;" : "=f"(f.x), "=f"(f.y) : "l"(v));
    return f;
}

// ---------------- CSR build ---------------------------------------------------
__global__ __launch_bounds__(256) void k_deg_count(const int* __restrict__ ei) {
    int i = blockIdx.x * blockDim.x + threadIdx.x;
    if (i >= EE / 4) return;
    int4 d4 = ((const int4*)(ei + EE))[i];
    atomicAdd(&d_deg[d4.x], 1);
    atomicAdd(&d_deg[d4.y], 1);
    atomicAdd(&d_deg[d4.z], 1);
    atomicAdd(&d_deg[d4.w], 1);
}

// Parallel segment allocation: per-block scan + one atomicAdd for base.
// Segments are NOT in node order (irrelevant: accessed via off/end only).
__global__ __launch_bounds__(256) void k_alloc() {
    __shared__ int wsum[8];
    __shared__ int sbase;
    int tid = threadIdx.x, lane = tid & 31, w = tid >> 5;
    int i = blockIdx.x * 256 + tid;
    int cnt = (i < NN) ? d_deg[i] + 1 : 0;      // +1 self loop
    int sc = cnt;
    #pragma unroll
    for (int o = 1; o < 32; o <<= 1) {
        int v = __shfl_up_sync(0xffffffffu, sc, o);
        if (lane >= o) sc += v;
    }
    if (lane == 31) wsum[w] = sc;
    __syncthreads();
    if (w == 0) {
        int s = (lane < 8) ? wsum[lane] : 0;
        #pragma unroll
        for (int o = 1; o < 8; o <<= 1) {
            int v = __shfl_up_sync(0xffffffffu, s, o);
            if (lane >= o) s += v;
        }
        if (lane < 8) wsum[lane] = s;
        if (lane == 7) sbase = atomicAdd(&d_total, s);
    }
    __syncthreads();
    if (i < NN) {
        int base = sbase + (w > 0 ? wsum[w - 1] : 0) + sc - cnt;
        d_off[i] = base;
        d_cursor[i] = base;
        d_end[i] = base + cnt;
        d_deg[i] = 0;                            // restore for next replay
    }
}

__global__ __launch_bounds__(256) void k_fill(const int* __restrict__ ei) {
    int i = blockIdx.x * blockDim.x + threadIdx.x;
    if (i < EE / 4) {
        int4 s4 = ((const int4*)ei)[i];
        int4 t4 = ((const int4*)(ei + EE))[i];
        int p0 = atomicAdd(&d_cursor[t4.x], 1); d_csrc[p0] = s4.x;
        int p1 = atomicAdd(&d_cursor[t4.y], 1); d_csrc[p1] = s4.y;
        int p2 = atomicAdd(&d_cursor[t4.z], 1); d_csrc[p2] = s4.z;
        int p3 = atomicAdd(&d_cursor[t4.w], 1); d_csrc[p3] = s4.w;
    } else {
        int base = (i - EE / 4) * 4;
        #pragma unroll
        for (int r = 0; r < 4; r++) {
            int node = base + r;
            if (node < NN) {
                int pos = atomicAdd(&d_cursor[node], 1);
                d_csrc[pos] = node;
            }
        }
    }
}

// ---------------- GEMM1 + fused prep1 (persistent, W loaded once) ------------
#define XPAD 68
#define NTILE1 ((NN + 63) / 64)
__global__ __launch_bounds__(256) void k_gemm1(const float* __restrict__ x,
                                               const float* __restrict__ W1,
                                               const float* __restrict__ a_src,
                                               const float* __restrict__ a_dst) {
    __shared__ float Wsm[DIN * HIDN];                 // 32 KB
    __shared__ __align__(16) float xs[64 * XPAD];     // 17.4 KB
    __shared__ float sa_s[HIDN], sd_s[HIDN];
    int tid = threadIdx.x, lane = tid & 31, w = tid >> 5;
    for (int i = tid; i < DIN * HIDN; i += 256) Wsm[i] = W1[i];
    if (tid < HIDN) { sa_s[tid] = a_src[tid]; sd_s[tid] = a_dst[tid]; }
    __syncthreads();
    int cp = lane;
    int r0 = w * 8;
    float wa0 = sa_s[cp], wa1 = sa_s[cp + 32];
    float wd0 = sd_s[cp], wd1 = sd_s[cp + 32];
    int h0 = cp >> 4;

    for (int tile = blockIdx.x; tile < NTILE1; tile += gridDim.x) {
        int row0 = tile * 64;
        ull acc[4][2] = {{0ull,0ull},{0ull,0ull},{0ull,0ull},{0ull,0ull}};
        #pragma unroll
        for (int half = 0; half < 2; half++) {
            __syncthreads();
            for (int i = tid; i < 64 * 64; i += 256) {
                int rr = i >> 6, k = i & 63;
                int row = row0 + rr;
                xs[k * XPAD + rr] = (row < NN) ? x[row * DIN + half * 64 + k] : 0.f;
            }
            __syncthreads();
            int kw = half * 64;
            #pragma unroll 4
            for (int k = 0; k < 64; k++) {
                const float* xk = xs + k * XPAD + r0;
                ulonglong2 A = *(const ulonglong2*)xk;
                ulonglong2 B = *(const ulonglong2*)(xk + 4);
                ull w0d = pack2dup(Wsm[(kw + k) * HIDN + cp]);
                ull w1d = pack2dup(Wsm[(kw + k) * HIDN + cp + 32]);
                acc[0][0] = ffma2(A.x, w0d, acc[0][0]);
                acc[0][1] = ffma2(A.x, w1d, acc[0][1]);
                acc[1][0] = ffma2(A.y, w0d, acc[1][0]);
                acc[1][1] = ffma2(A.y, w1d, acc[1][1]);
                acc[2][0] = ffma2(B.x, w0d, acc[2][0]);
                acc[2][1] = ffma2(B.x, w1d, acc[2][1]);
                acc[3][0] = ffma2(B.y, w0d, acc[3][0]);
                acc[3][1] = ffma2(B.y, w1d, acc[3][1]);
            }
        }
        #pragma unroll
        for (int rp = 0; rp < 4; rp++) {
            float2 o0 = unpack2(acc[rp][0]);
            float2 o1 = unpack2(acc[rp][1]);
            #pragma unroll
            for (int half = 0; half < 2; half++) {
                int row = row0 + r0 + 2 * rp + half;
                if (row >= NN) continue;
                float vx = half ? o0.y : o0.x;
                float vy = half ? o1.y : o1.x;
                d_xl1p[row * 32 + cp] = make_float2(vx, vy);
                float sax = vx * wa0, say = vy * wa1;
                float sdx = vx * wd0, sdy = vy * wd1;
                #pragma unroll
                for (int o = 8; o > 0; o >>= 1) {
                    sax += __shfl_xor_sync(0xffffffffu, sax, o);
                    say += __shfl_xor_sync(0xffffffffu, say, o);
                    sdx += __shfl_xor_sync(0xffffffffu, sdx, o);
                    sdy += __shfl_xor_sync(0xffffffffu, sdy, o);
                }
                if ((lane & 15) == 0) {
                    d_es1[row * 4 + h0]     = sax;
                    d_es1[row * 4 + h0 + 2] = say;
                    d_ed1[row * 4 + h0]     = sdx;
                    d_ed1[row * 4 + h0 + 2] = sdy;
                }
            }
        }
    }
}

// ---------------- layer-1 GAT + fused BN1 stats ------------------------------
__global__ __launch_bounds__(256) void k_gat1() {
    __shared__ float s_sum[HIDN], s_sq[HIDN];
    __shared__ float4 ps[8][32];   // {p0,p2,p1,p3}
    __shared__ int    se[8][32];
    int tid = threadIdx.x;
    int lane = tid & 31, w = tid >> 5;
    if (tid < HIDN) { s_sum[tid] = 0.f; s_sq[tid] = 0.f; }
    __syncthreads();
    int h0 = lane >> 4;
    const float2* pb = (const float2*)&ps[w][0];
    for (int n = blockIdx.x * 8 + w; n < NN; n += gridDim.x * 8) {
        int start = d_off[n], end = d_end[n];
        float4 ed = *(const float4*)&d_ed1[n * 4];
        float acc0 = 0.f, acc1 = 0.f;
        float s0 = 0.f, s1 = 0.f, s2 = 0.f, s3 = 0.f;
        for (int j0 = start; j0 < end; j0 += 32) {
            int j = j0 + lane;
            int cnt = min(32, end - j0);
            int s = 0;
            float p0 = 0.f, p1 = 0.f, p2 = 0.f, p3 = 0.f;
            if (j < end) {
                s = d_csrc[j];
                float4 es = *(const float4*)&d_es1[s * 4];
                p0 = __expf(lrelu(es.x + ed.x));
                p1 = __expf(lrelu(es.y + ed.y));
                p2 = __expf(lrelu(es.z + ed.z));
                p3 = __expf(lrelu(es.w + ed.w));
            }
            s0 += p0; s1 += p1; s2 += p2; s3 += p3;
            ps[w][lane] = make_float4(p0, p2, p1, p3);
            se[w][lane] = s;
            __syncwarp();
            int t = 0;
            for (; t + 4 <= cnt; t += 4) {
                int ssb[4]; float2 pq[4]; float2 f[4];
                #pragma unroll
                for (int u = 0; u < 4; u++) {
                    ssb[u] = se[w][t + u];
                    pq[u]  = pb[2 * (t + u) + h0];
                }
                #pragma unroll
                for (int u = 0; u < 4; u++) f[u] = d_xl1p[ssb[u] * 32 + lane];
                #pragma unroll
                for (int u = 0; u < 4; u++) {
                    acc0 += pq[u].x * f[u].x;
                    acc1 += pq[u].y * f[u].y;
                }
            }
            for (; t < cnt; t++) {
                int ss = se[w][t];
                float2 pq = pb[2 * t + h0];
                float2 f = d_xl1p[ss * 32 + lane];
                acc0 += pq.x * f.x;
                acc1 += pq.y * f.y;
            }
            __syncwarp();
        }
        #pragma unroll
        for (int o = 16; o > 0; o >>= 1) {
            s0 += __shfl_xor_sync(0xffffffffu, s0, o);
            s1 += __shfl_xor_sync(0xffffffffu, s1, o);
            s2 += __shfl_xor_sync(0xffffffffu, s2, o);
            s3 += __shfl_xor_sync(0xffffffffu, s3, o);
        }
        float sA = h0 ? s1 : s0;
        float sB = h0 ? s3 : s2;
        float v0 = acc0 / (sA + 1e-16f);
        float v1 = acc1 / (sB + 1e-16f);
        d_h1[n * HIDN + lane]      = v0;
        d_h1[n * HIDN + 32 + lane] = v1;
        atomicAdd(&s_sum[lane], v0);       atomicAdd(&s_sum[32 + lane], v1);
        atomicAdd(&s_sq[lane], v0 * v0);   atomicAdd(&s_sq[32 + lane], v1 * v1);
    }
    __syncthreads();
    if (tid < HIDN) {
        atomicAdd(&d_stats1[tid], s_sum[tid]);
        atomicAdd(&d_stats1[HIDN + tid], s_sq[tid]);
    }
}

// ---------------- GEMM2 (BN1 fused) + fused prep2, 16-row tiles --------------
__global__ __launch_bounds__(256) void k_gemm2(const float* __restrict__ W2,
                                               const float* __restrict__ g1,
                                               const float* __restrict__ be1,
                                               const float* __restrict__ a_src2,
                                               const float* __restrict__ a_dst2) {
    __shared__ float Ws[HIDN * OUTC];
    __shared__ float xs[16][HIDN];
    __shared__ float bnm[HIDN], bna[HIDN];
    int tid = threadIdx.x;
    for (int i = tid; i < HIDN * OUTC; i += 256) Ws[i] = W2[i];
    if (tid < HIDN) {
        float mu  = d_stats1[tid] * (1.0f / NN);
        float var = d_stats1[HIDN + tid] * (1.0f / NN) - mu * mu;
        float m = rsqrtf(var + BN_EPS) * g1[tid];
        bnm[tid] = m;
        bna[tid] = be1[tid] - mu * m;
    }
    int col = tid & 31;
    int r   = tid >> 5;
    float a2s = a_src2[col], a2d = a_dst2[col];
    for (int row0 = blockIdx.x * 16; row0 < NN; row0 += gridDim.x * 16) {
        __syncthreads();
        for (int i = tid; i < 16 * HIDN; i += 256) {
            int rr = i >> 6, k = i & 63;
            int row = row0 + rr;
            float hv = (row < NN) ? d_h1[row * HIDN + k] : 0.f;
            xs[rr][k] = fmaxf(fmaf(hv, bnm[k], bna[k]), 0.f);
        }
        __syncthreads();
        #pragma unroll
        for (int half = 0; half < 2; half++) {
            int rr = r + half * 8;
            int row = row0 + rr;
            if (row < NN) {
                float acc = 0.f;
                #pragma unroll
                for (int k = 0; k < HIDN; k++) acc = fmaf(xs[rr][k], Ws[k * OUTC + col], acc);
                d_xl2[row * OUTC + col] = acc;
                float es = acc * a2s, edv = acc * a2d;
                #pragma unroll
                for (int o = 16; o > 0; o >>= 1) {
                    es  += __shfl_xor_sync(0xffffffffu, es, o);
                    edv += __shfl_xor_sync(0xffffffffu, edv, o);
                }
                if (col == 0) { d_es2[row] = es; d_ed2[row] = edv; }
            }
        }
    }
}

// ---------------- layer-2 GAT + fused BN2 stats ------------------------------
__global__ __launch_bounds__(256) void k_gat2() {
    __shared__ float s_sum[OUTC], s_sq[OUTC];
    int tid = threadIdx.x;
    int lane = tid & 31, w = tid >> 5;
    if (tid < OUTC) { s_sum[tid] = 0.f; s_sq[tid] = 0.f; }
    __syncthreads();
    for (int n = blockIdx.x * 8 + w; n < NN; n += gridDim.x * 8) {
        int start = d_off[n], end = d_end[n];
        float ed = d_ed2[n];
        float acc = 0.f, psum = 0.f;
        for (int j0 = start; j0 < end; j0 += 32) {
            int j = j0 + lane;
            int cnt = min(32, end - j0);
            int s = 0;
            float p = 0.f;
            if (j < end) {
                s = d_csrc[j];
                p = __expf(lrelu(d_es2[s] + ed));
            }
            psum += p;
            int t = 0;
            for (; t + 4 <= cnt; t += 4) {
                int ssb[4]; float pp[4], f[4];
                #pragma unroll
                for (int u = 0; u < 4; u++) {
                    ssb[u] = __shfl_sync(0xffffffffu, s, t + u);
                    pp[u]  = __shfl_sync(0xffffffffu, p, t + u);
                }
                #pragma unroll
                for (int u = 0; u < 4; u++) f[u] = d_xl2[ssb[u] * OUTC + lane];
                #pragma unroll
                for (int u = 0; u < 4; u++) acc += pp[u] * f[u];
            }
            for (; t < cnt; t++) {
                int   ss = __shfl_sync(0xffffffffu, s, t);
                float pp = __shfl_sync(0xffffffffu, p, t);
                acc += pp * d_xl2[ss * OUTC + lane];
            }
        }
        #pragma unroll
        for (int o = 16; o > 0; o >>= 1)
            psum += __shfl_xor_sync(0xffffffffu, psum, o);
        float v = acc / (psum + 1e-16f);
        d_h2[n * OUTC + lane] = v;
        atomicAdd(&s_sum[lane], v);
        atomicAdd(&s_sq[lane], v * v);
    }
    __syncthreads();
    if (tid < OUTC) {
        atomicAdd(&d_stats2[tid], s_sum[tid]);
        atomicAdd(&d_stats2[OUTC + tid], s_sq[tid]);
    }
}

// ---------------- BN2 + node_emb + pooling (smem-accumulated) ----------------
#define PB_NODES 256
__global__ __launch_bounds__(256) void k_bn2_pool(const float* __restrict__ g2,
                                                  const float* __restrict__ be2,
                                                  const int* __restrict__ batch,
                                                  float* __restrict__ out) {
    __shared__ float lsum[NB * OUTC];
    __shared__ float lmax[NB * OUTC];
    __shared__ float lcnt[NB];
    int tid = threadIdx.x;
    for (int i = tid; i < NB * OUTC; i += 256) { lsum[i] = 0.f; lmax[i] = NEG_INF(); }
    if (tid < NB) lcnt[tid] = 0.f;
    int col = tid & 31;
    float mu  = d_stats2[col] * (1.0f / NN);
    float var = d_stats2[OUTC + col] * (1.0f / NN) - mu * mu;
    float m = rsqrtf(var + BN_EPS) * g2[col];
    float a = be2[col] - mu * m;
    int n0 = blockIdx.x * PB_NODES;
    __syncthreads();
    #pragma unroll 4
    for (int k = 0; k < PB_NODES * OUTC / 256; k++) {
        int idx = n0 * OUTC + k * 256 + tid;
        int node = idx >> 5;
        if (node < NN) {
            float v = fmaf(d_h2[idx], m, a);
            out[idx] = v;
            int b = batch[node];
            atomicAdd(&lsum[b * OUTC + col], v);
            atomicMaxF(&lmax[b * OUTC + col], v);
            if (col == 0) atomicAdd(&lcnt[b], 1.f);
        }
    }
    __syncthreads();
    int nlast = min(n0 + PB_NODES, NN) - 1;
    int bmin = batch[n0], bmax = batch[nlast];
    for (int j = tid; j < (bmax - bmin + 1) * OUTC; j += 256) {
        int b = bmin + (j >> 5), c = j & 31;
        float sv = lsum[b * OUTC + c];
        if (sv != 0.f) atomicAdd(&d_gsum[b * OUTC + c], sv);
        float mv = lmax[b * OUTC + c];
        if (mv > NEG_INF()) atomicMaxF(&d_gmax[b * OUTC + c], mv);
        if (c == 0) {
            float cv = lcnt[b];
            if (cv != 0.f) atomicAdd(&d_gcnt[b], cv);
        }
    }
}

// ---------------- final MLP + scratch restore --------------------------------
__global__ __launch_bounds__(256) void k_final(const float* __restrict__ fcW1,
                                               const float* __restrict__ fcb1,
                                               const float* __restrict__ fcW2,
                                               const float* __restrict__ fcb2,
                                               float* __restrict__ out) {
    __shared__ float g[NB * 2 * OUTC];
    __shared__ float t[NB * OUTC];
    int tid = threadIdx.x;
    for (int i = tid; i < NB * 2 * OUTC; i += 256) {
        int b = i >> 6, j = i & 63;
        float v;
        if (j < OUTC) {
            v = d_gsum[b * OUTC + j] / fmaxf(d_gcnt[b], 1.f);
        } else {
            v = d_gmax[b * OUTC + (j - OUTC)];
            if (v < -3e37f) v = 0.f;
        }
        g[i] = v;
    }
    __syncthreads();
    // restore accumulators for the next replay
    for (int i = tid; i < NB * OUTC; i += 256) { d_gsum[i] = 0.f; d_gmax[i] = NEG_INF(); }
    if (tid < NB) d_gcnt[tid] = 0.f;
    if (tid < 2 * HIDN) d_stats1[tid] = 0.f;
    if (tid < 2 * OUTC) d_stats2[tid] = 0.f;
    if (tid == 0) d_total = 0;
    // MLP
    for (int i = tid; i < NB * OUTC; i += 256) {
        int b = i >> 5, o = i & 31;
        float acc = fcb1[o];
        #pragma unroll
        for (int j = 0; j < 2 * OUTC; j++) acc = fmaf(g[b * 64 + j], fcW1[j * OUTC + o], acc);
        t[i] = fmaxf(acc, 0.f);
    }
    __syncthreads();
    for (int i = tid; i < NB * OUTC; i += 256) {
        int b = i >> 5, o = i & 31;
        float acc = fcb2[o];
        #pragma unroll
        for (int j = 0; j < OUTC; j++) acc = fmaf(t[b * OUTC + j], fcW2[j * OUTC + o], acc);
        out[NN * OUTC + i] = acc;
    }
}

// =============================================================================
extern "C" void kernel_launch(void* const* d_in, const int* in_sizes, int n_in,
                              void* d_out, int out_size) {
    const float* x      = (const float*)d_in[0];
    const int*   ei     = (const int*)  d_in[1];
    const int*   batch  = (const int*)  d_in[2];
    const float* W1     = (const float*)d_in[3];
    const float* a_src1 = (const float*)d_in[4];
    const float* a_dst1 = (const float*)d_in[5];
    const float* g1     = (const float*)d_in[7];
    const float* be1    = (const float*)d_in[8];
    const float* W2     = (const float*)d_in[9];
    const float* a_src2 = (const float*)d_in[10];
    const float* a_dst2 = (const float*)d_in[11];
    const float* g2     = (const float*)d_in[13];
    const float* be2    = (const float*)d_in[14];
    const float* fcW1   = (const float*)d_in[15];
    const float* fcb1   = (const float*)d_in[16];
    const float* fcW2   = (const float*)d_in[17];
    const float* fcb2   = (const float*)d_in[18];
    float* out = (float*)d_out;

    k_deg_count<<<(EE / 4 + 255) / 256, 256>>>(ei);
    k_alloc<<<(NN + 255) / 256, 256>>>();
    k_fill<<<((EE / 4 + (NN + 3) / 4) + 255) / 256, 256>>>(ei);
    k_gemm1<<<592, 256>>>(x, W1, a_src1, a_dst1);   // launch #4: ncu capture slot

    k_gat1<<<592, 256>>>();

    k_gemm2<<<592, 256>>>(W2, g1, be1, a_src2, a_dst2);
    k_gat2<<<592, 256>>>();
    k_bn2_pool<<<(NN + PB_NODES - 1) / PB_NODES, 256>>>(g2, be2, batch, out);

    k_final<<<1, 256>>>(fcW1, fcb1, fcW2, fcb2, out);
}

// round 17
// speedup vs baseline: 1.5336x; 1.0686x over previous
#include <cuda_runtime.h>
#include <cuda_bf16.h>

#define NN   50000
#define EE   800000
#define ET   (EE + NN)
#define DIN  128
#define HIDN 64
#define OUTC 32
#define NB   64
#define NHEAD 4

#define NEG_SLOPE 0.2f
#define BN_EPS 1e-5f

// ---------------- scratch (zero-initialized at module load; k_final restores) -
__device__ float2 d_xl1p[NN * 32];     // paired: [n][c] = (col c, col c+32)
__device__ float d_es1[NN * NHEAD];
__device__ float d_ed1[NN * NHEAD];
__device__ float d_h1[NN * HIDN];
__device__ float d_stats1[2 * HIDN];   // reset by k_final

__device__ float d_xl2[NN * OUTC];
__device__ float d_es2[NN];
__device__ float d_ed2[NN];
__device__ float d_h2[NN * OUTC];
__device__ float d_stats2[2 * OUTC];   // reset by k_final

__device__ float d_gsum[NB * OUTC];    // reset by k_final
__device__ float d_gmax[NB * OUTC];    // reset by k_final (to -inf)
__device__ float d_gcnt[NB];           // reset by k_final

// CSR (by dst)
__device__ int d_deg[NN];              // reset by k_alloc
__device__ int d_off[NN];
__device__ int d_end[NN];
__device__ int d_cursor[NN];
__device__ int d_csrc[ET];
__device__ int d_total;                // reset by k_final

__device__ __forceinline__ float NEG_INF() { return __int_as_float(0xff800000); }

__device__ __forceinline__ void atomicMaxF(float* addr, float v) {
    if (v >= 0.0f) atomicMax((int*)addr, __float_as_int(v));
    else           atomicMin((unsigned int*)addr, __float_as_uint(v));
}

__device__ __forceinline__ float lrelu(float e) { return e > 0.f ? e : NEG_SLOPE * e; }

typedef unsigned long long ull;
__device__ __forceinline__ ull pack2dup(float x) {
    ull r;
    asm("mov.b64 %0, {%1,%2};" : "=l"(r) : "f"(x), "f"(x));
    return r;
}
__device__ __forceinline__ ull ffma2(ull a, ull b, ull c) {
    ull d;
    asm("fma.rn.f32x2 %0, %1, %2, %3;" : "=l"(d) : "l"(a), "l"(b), "l"(c));
    return d;
}
__device__ __forceinline__ float2 unpack2(ull v) {
    float2 f;
    asm("mov.b64 {%0,%1}, %2;" : "=f"(f.x), "=f"(f.y) : "l"(v));
    return f;
}

// ---------------- CSR build ---------------------------------------------------
__global__ __launch_bounds__(256) void k_deg_count(const int* __restrict__ ei) {
    int i = blockIdx.x * blockDim.x + threadIdx.x;
    if (i >= EE / 4) return;
    int4 d4 = ((const int4*)(ei + EE))[i];
    atomicAdd(&d_deg[d4.x], 1);
    atomicAdd(&d_deg[d4.y], 1);
    atomicAdd(&d_deg[d4.z], 1);
    atomicAdd(&d_deg[d4.w], 1);
}

// Parallel segment allocation; also emits the self-loop entry directly.
__global__ __launch_bounds__(256) void k_alloc() {
    __shared__ int wsum[8];
    __shared__ int sbase;
    int tid = threadIdx.x, lane = tid & 31, w = tid >> 5;
    int i = blockIdx.x * 256 + tid;
    int cnt = (i < NN) ? d_deg[i] + 1 : 0;      // +1 self loop
    int sc = cnt;
    #pragma unroll
    for (int o = 1; o < 32; o <<= 1) {
        int v = __shfl_up_sync(0xffffffffu, sc, o);
        if (lane >= o) sc += v;
    }
    if (lane == 31) wsum[w] = sc;
    __syncthreads();
    if (w == 0) {
        int s = (lane < 8) ? wsum[lane] : 0;
        #pragma unroll
        for (int o = 1; o < 8; o <<= 1) {
            int v = __shfl_up_sync(0xffffffffu, s, o);
            if (lane >= o) s += v;
        }
        if (lane < 8) wsum[lane] = s;
        if (lane == 7) sbase = atomicAdd(&d_total, s);
    }
    __syncthreads();
    if (i < NN) {
        int base = sbase + (w > 0 ? wsum[w - 1] : 0) + sc - cnt;
        d_off[i] = base;
        d_csrc[base] = i;                        // self loop emitted here
        d_cursor[i] = base + 1;
        d_end[i] = base + cnt;
        d_deg[i] = 0;                            // restore for next replay
    }
}

__global__ __launch_bounds__(256) void k_fill(const int* __restrict__ ei) {
    int i = blockIdx.x * blockDim.x + threadIdx.x;
    if (i >= EE / 4) return;
    int4 s4 = ((const int4*)ei)[i];
    int4 t4 = ((const int4*)(ei + EE))[i];
    int p0 = atomicAdd(&d_cursor[t4.x], 1); d_csrc[p0] = s4.x;
    int p1 = atomicAdd(&d_cursor[t4.y], 1); d_csrc[p1] = s4.y;
    int p2 = atomicAdd(&d_cursor[t4.z], 1); d_csrc[p2] = s4.z;
    int p3 = atomicAdd(&d_cursor[t4.w], 1); d_csrc[p3] = s4.w;
}

// ---------------- GEMM1 + fused prep1 (persistent; UNCHANGED control) --------
#define XPAD 68
#define NTILE1 ((NN + 63) / 64)
__global__ __launch_bounds__(256) void k_gemm1(const float* __restrict__ x,
                                               const float* __restrict__ W1,
                                               const float* __restrict__ a_src,
                                               const float* __restrict__ a_dst) {
    __shared__ float Wsm[DIN * HIDN];                 // 32 KB
    __shared__ __align__(16) float xs[64 * XPAD];     // 17.4 KB
    __shared__ float sa_s[HIDN], sd_s[HIDN];
    int tid = threadIdx.x, lane = tid & 31, w = tid >> 5;
    for (int i = tid; i < DIN * HIDN; i += 256) Wsm[i] = W1[i];
    if (tid < HIDN) { sa_s[tid] = a_src[tid]; sd_s[tid] = a_dst[tid]; }
    __syncthreads();
    int cp = lane;
    int r0 = w * 8;
    float wa0 = sa_s[cp], wa1 = sa_s[cp + 32];
    float wd0 = sd_s[cp], wd1 = sd_s[cp + 32];
    int h0 = cp >> 4;

    for (int tile = blockIdx.x; tile < NTILE1; tile += gridDim.x) {
        int row0 = tile * 64;
        ull acc[4][2] = {{0ull,0ull},{0ull,0ull},{0ull,0ull},{0ull,0ull}};
        #pragma unroll
        for (int half = 0; half < 2; half++) {
            __syncthreads();
            for (int i = tid; i < 64 * 64; i += 256) {
                int rr = i >> 6, k = i & 63;
                int row = row0 + rr;
                xs[k * XPAD + rr] = (row < NN) ? x[row * DIN + half * 64 + k] : 0.f;
            }
            __syncthreads();
            int kw = half * 64;
            #pragma unroll 4
            for (int k = 0; k < 64; k++) {
                const float* xk = xs + k * XPAD + r0;
                ulonglong2 A = *(const ulonglong2*)xk;
                ulonglong2 B = *(const ulonglong2*)(xk + 4);
                ull w0d = pack2dup(Wsm[(kw + k) * HIDN + cp]);
                ull w1d = pack2dup(Wsm[(kw + k) * HIDN + cp + 32]);
                acc[0][0] = ffma2(A.x, w0d, acc[0][0]);
                acc[0][1] = ffma2(A.x, w1d, acc[0][1]);
                acc[1][0] = ffma2(A.y, w0d, acc[1][0]);
                acc[1][1] = ffma2(A.y, w1d, acc[1][1]);
                acc[2][0] = ffma2(B.x, w0d, acc[2][0]);
                acc[2][1] = ffma2(B.x, w1d, acc[2][1]);
                acc[3][0] = ffma2(B.y, w0d, acc[3][0]);
                acc[3][1] = ffma2(B.y, w1d, acc[3][1]);
            }
        }
        #pragma unroll
        for (int rp = 0; rp < 4; rp++) {
            float2 o0 = unpack2(acc[rp][0]);
            float2 o1 = unpack2(acc[rp][1]);
            #pragma unroll
            for (int half = 0; half < 2; half++) {
                int row = row0 + r0 + 2 * rp + half;
                if (row >= NN) continue;
                float vx = half ? o0.y : o0.x;
                float vy = half ? o1.y : o1.x;
                d_xl1p[row * 32 + cp] = make_float2(vx, vy);
                float sax = vx * wa0, say = vy * wa1;
                float sdx = vx * wd0, sdy = vy * wd1;
                #pragma unroll
                for (int o = 8; o > 0; o >>= 1) {
                    sax += __shfl_xor_sync(0xffffffffu, sax, o);
                    say += __shfl_xor_sync(0xffffffffu, say, o);
                    sdx += __shfl_xor_sync(0xffffffffu, sdx, o);
                    sdy += __shfl_xor_sync(0xffffffffu, sdy, o);
                }
                if ((lane & 15) == 0) {
                    d_es1[row * 4 + h0]     = sax;
                    d_es1[row * 4 + h0 + 2] = say;
                    d_ed1[row * 4 + h0]     = sdx;
                    d_ed1[row * 4 + h0 + 2] = sdy;
                }
            }
        }
    }
}

// ---------------- layer-1 GAT (pipelined gather) + fused BN1 stats -----------
__global__ __launch_bounds__(256) void k_gat1() {
    __shared__ float s_sum[HIDN], s_sq[HIDN];
    __shared__ float4 ps[8][32];   // {p0,p2,p1,p3}
    __shared__ int    se[8][32];
    int tid = threadIdx.x;
    int lane = tid & 31, w = tid >> 5;
    if (tid < HIDN) { s_sum[tid] = 0.f; s_sq[tid] = 0.f; }
    __syncthreads();
    int h0 = lane >> 4;
    const float2* pb = (const float2*)&ps[w][0];
    for (int n = blockIdx.x * 8 + w; n < NN; n += gridDim.x * 8) {
        int start = d_off[n], end = d_end[n];
        float4 ed = *(const float4*)&d_ed1[n * 4];
        float acc0 = 0.f, acc1 = 0.f;
        float s0 = 0.f, s1 = 0.f, s2 = 0.f, s3 = 0.f;
        // prologue prefetch: chunk 0's scattered gather
        int s_cur = 0;
        float4 es_cur = make_float4(0.f, 0.f, 0.f, 0.f);
        if (start + lane < end) {
            s_cur = d_csrc[start + lane];
            es_cur = *(const float4*)&d_es1[s_cur * 4];
        }
        for (int j0 = start; j0 < end; j0 += 32) {
            int cnt = min(32, end - j0);
            float p0 = 0.f, p1 = 0.f, p2 = 0.f, p3 = 0.f;
            if (j0 + lane < end) {
                p0 = __expf(lrelu(es_cur.x + ed.x));
                p1 = __expf(lrelu(es_cur.y + ed.y));
                p2 = __expf(lrelu(es_cur.z + ed.z));
                p3 = __expf(lrelu(es_cur.w + ed.w));
            }
            s0 += p0; s1 += p1; s2 += p2; s3 += p3;
            ps[w][lane] = make_float4(p0, p2, p1, p3);
            se[w][lane] = s_cur;
            __syncwarp();
            // prefetch NEXT chunk's scattered gather (hidden behind broadcast loop)
            int jn = j0 + 32 + lane;
            int s_nxt = 0;
            float4 es_nxt = make_float4(0.f, 0.f, 0.f, 0.f);
            if (jn < end) {
                s_nxt = d_csrc[jn];
                es_nxt = *(const float4*)&d_es1[s_nxt * 4];
            }
            int t = 0;
            for (; t + 4 <= cnt; t += 4) {
                int ssb[4]; float2 pq[4]; float2 f[4];
                #pragma unroll
                for (int u = 0; u < 4; u++) {
                    ssb[u] = se[w][t + u];
                    pq[u]  = pb[2 * (t + u) + h0];
                }
                #pragma unroll
                for (int u = 0; u < 4; u++) f[u] = d_xl1p[ssb[u] * 32 + lane];
                #pragma unroll
                for (int u = 0; u < 4; u++) {
                    acc0 += pq[u].x * f[u].x;
                    acc1 += pq[u].y * f[u].y;
                }
            }
            for (; t < cnt; t++) {
                int ss = se[w][t];
                float2 pq = pb[2 * t + h0];
                float2 f = d_xl1p[ss * 32 + lane];
                acc0 += pq.x * f.x;
                acc1 += pq.y * f.y;
            }
            __syncwarp();
            s_cur = s_nxt;
            es_cur = es_nxt;
        }
        #pragma unroll
        for (int o = 16; o > 0; o >>= 1) {
            s0 += __shfl_xor_sync(0xffffffffu, s0, o);
            s1 += __shfl_xor_sync(0xffffffffu, s1, o);
            s2 += __shfl_xor_sync(0xffffffffu, s2, o);
            s3 += __shfl_xor_sync(0xffffffffu, s3, o);
        }
        float sA = h0 ? s1 : s0;
        float sB = h0 ? s3 : s2;
        float v0 = acc0 / (sA + 1e-16f);
        float v1 = acc1 / (sB + 1e-16f);
        d_h1[n * HIDN + lane]      = v0;
        d_h1[n * HIDN + 32 + lane] = v1;
        atomicAdd(&s_sum[lane], v0);       atomicAdd(&s_sum[32 + lane], v1);
        atomicAdd(&s_sq[lane], v0 * v0);   atomicAdd(&s_sq[32 + lane], v1 * v1);
    }
    __syncthreads();
    if (tid < HIDN) {
        atomicAdd(&d_stats1[tid], s_sum[tid]);
        atomicAdd(&d_stats1[HIDN + tid], s_sq[tid]);
    }
}

// ---------------- GEMM2 (BN1 fused) + fused prep2, 16-row tiles --------------
__global__ __launch_bounds__(256) void k_gemm2(const float* __restrict__ W2,
                                               const float* __restrict__ g1,
                                               const float* __restrict__ be1,
                                               const float* __restrict__ a_src2,
                                               const float* __restrict__ a_dst2) {
    __shared__ float Ws[HIDN * OUTC];
    __shared__ float xs[16][HIDN];
    __shared__ float bnm[HIDN], bna[HIDN];
    int tid = threadIdx.x;
    for (int i = tid; i < HIDN * OUTC; i += 256) Ws[i] = W2[i];
    if (tid < HIDN) {
        float mu  = d_stats1[tid] * (1.0f / NN);
        float var = d_stats1[HIDN + tid] * (1.0f / NN) - mu * mu;
        float m = rsqrtf(var + BN_EPS) * g1[tid];
        bnm[tid] = m;
        bna[tid] = be1[tid] - mu * m;
    }
    int col = tid & 31;
    int r   = tid >> 5;
    float a2s = a_src2[col], a2d = a_dst2[col];
    for (int row0 = blockIdx.x * 16; row0 < NN; row0 += gridDim.x * 16) {
        __syncthreads();
        for (int i = tid; i < 16 * HIDN; i += 256) {
            int rr = i >> 6, k = i & 63;
            int row = row0 + rr;
            float hv = (row < NN) ? d_h1[row * HIDN + k] : 0.f;
            xs[rr][k] = fmaxf(fmaf(hv, bnm[k], bna[k]), 0.f);
        }
        __syncthreads();
        #pragma unroll
        for (int half = 0; half < 2; half++) {
            int rr = r + half * 8;
            int row = row0 + rr;
            if (row < NN) {
                float acc = 0.f;
                #pragma unroll
                for (int k = 0; k < HIDN; k++) acc = fmaf(xs[rr][k], Ws[k * OUTC + col], acc);
                d_xl2[row * OUTC + col] = acc;
                float es = acc * a2s, edv = acc * a2d;
                #pragma unroll
                for (int o = 16; o > 0; o >>= 1) {
                    es  += __shfl_xor_sync(0xffffffffu, es, o);
                    edv += __shfl_xor_sync(0xffffffffu, edv, o);
                }
                if (col == 0) { d_es2[row] = es; d_ed2[row] = edv; }
            }
        }
    }
}

// ---------------- layer-2 GAT (pipelined gather) + fused BN2 stats -----------
__global__ __launch_bounds__(256) void k_gat2() {
    __shared__ float s_sum[OUTC], s_sq[OUTC];
    int tid = threadIdx.x;
    int lane = tid & 31, w = tid >> 5;
    if (tid < OUTC) { s_sum[tid] = 0.f; s_sq[tid] = 0.f; }
    __syncthreads();
    for (int n = blockIdx.x * 8 + w; n < NN; n += gridDim.x * 8) {
        int start = d_off[n], end = d_end[n];
        float ed = d_ed2[n];
        float acc = 0.f, psum = 0.f;
        // prologue prefetch
        int s_cur = 0;
        float esv = 0.f;
        if (start + lane < end) {
            s_cur = d_csrc[start + lane];
            esv = d_es2[s_cur];
        }
        for (int j0 = start; j0 < end; j0 += 32) {
            int cnt = min(32, end - j0);
            float p = 0.f;
            if (j0 + lane < end) p = __expf(lrelu(esv + ed));
            psum += p;
            // prefetch next chunk
            int jn = j0 + 32 + lane;
            int s_nxt = 0;
            float es_nxt = 0.f;
            if (jn < end) {
                s_nxt = d_csrc[jn];
                es_nxt = d_es2[s_nxt];
            }
            int t = 0;
            for (; t + 4 <= cnt; t += 4) {
                int ssb[4]; float pp[4], f[4];
                #pragma unroll
                for (int u = 0; u < 4; u++) {
                    ssb[u] = __shfl_sync(0xffffffffu, s_cur, t + u);
                    pp[u]  = __shfl_sync(0xffffffffu, p, t + u);
                }
                #pragma unroll
                for (int u = 0; u < 4; u++) f[u] = d_xl2[ssb[u] * OUTC + lane];
                #pragma unroll
                for (int u = 0; u < 4; u++) acc += pp[u] * f[u];
            }
            for (; t < cnt; t++) {
                int   ss = __shfl_sync(0xffffffffu, s_cur, t);
                float pp = __shfl_sync(0xffffffffu, p, t);
                acc += pp * d_xl2[ss * OUTC + lane];
            }
            s_cur = s_nxt;
            esv = es_nxt;
        }
        #pragma unroll
        for (int o = 16; o > 0; o >>= 1)
            psum += __shfl_xor_sync(0xffffffffu, psum, o);
        float v = acc / (psum + 1e-16f);
        d_h2[n * OUTC + lane] = v;
        atomicAdd(&s_sum[lane], v);
        atomicAdd(&s_sq[lane], v * v);
    }
    __syncthreads();
    if (tid < OUTC) {
        atomicAdd(&d_stats2[tid], s_sum[tid]);
        atomicAdd(&d_stats2[OUTC + tid], s_sq[tid]);
    }
}

// ---------------- BN2 + node_emb + pooling (smem-accumulated) ----------------
#define PB_NODES 256
__global__ __launch_bounds__(256) void k_bn2_pool(const float* __restrict__ g2,
                                                  const float* __restrict__ be2,
                                                  const int* __restrict__ batch,
                                                  float* __restrict__ out) {
    __shared__ float lsum[NB * OUTC];
    __shared__ float lmax[NB * OUTC];
    __shared__ float lcnt[NB];
    int tid = threadIdx.x;
    for (int i = tid; i < NB * OUTC; i += 256) { lsum[i] = 0.f; lmax[i] = NEG_INF(); }
    if (tid < NB) lcnt[tid] = 0.f;
    int col = tid & 31;
    float mu  = d_stats2[col] * (1.0f / NN);
    float var = d_stats2[OUTC + col] * (1.0f / NN) - mu * mu;
    float m = rsqrtf(var + BN_EPS) * g2[col];
    float a = be2[col] - mu * m;
    int n0 = blockIdx.x * PB_NODES;
    __syncthreads();
    #pragma unroll 4
    for (int k = 0; k < PB_NODES * OUTC / 256; k++) {
        int idx = n0 * OUTC + k * 256 + tid;
        int node = idx >> 5;
        if (node < NN) {
            float v = fmaf(d_h2[idx], m, a);
            out[idx] = v;
            int b = batch[node];
            atomicAdd(&lsum[b * OUTC + col], v);
            atomicMaxF(&lmax[b * OUTC + col], v);
            if (col == 0) atomicAdd(&lcnt[b], 1.f);
        }
    }
    __syncthreads();
    int nlast = min(n0 + PB_NODES, NN) - 1;
    int bmin = batch[n0], bmax = batch[nlast];
    for (int j = tid; j < (bmax - bmin + 1) * OUTC; j += 256) {
        int b = bmin + (j >> 5), c = j & 31;
        float sv = lsum[b * OUTC + c];
        if (sv != 0.f) atomicAdd(&d_gsum[b * OUTC + c], sv);
        float mv = lmax[b * OUTC + c];
        if (mv > NEG_INF()) atomicMaxF(&d_gmax[b * OUTC + c], mv);
        if (c == 0) {
            float cv = lcnt[b];
            if (cv != 0.f) atomicAdd(&d_gcnt[b], cv);
        }
    }
}

// ---------------- final MLP + scratch restore --------------------------------
__global__ __launch_bounds__(256) void k_final(const float* __restrict__ fcW1,
                                               const float* __restrict__ fcb1,
                                               const float* __restrict__ fcW2,
                                               const float* __restrict__ fcb2,
                                               float* __restrict__ out) {
    __shared__ float g[NB * 2 * OUTC];
    __shared__ float t[NB * OUTC];
    int tid = threadIdx.x;
    for (int i = tid; i < NB * 2 * OUTC; i += 256) {
        int b = i >> 6, j = i & 63;
        float v;
        if (j < OUTC) {
            v = d_gsum[b * OUTC + j] / fmaxf(d_gcnt[b], 1.f);
        } else {
            v = d_gmax[b * OUTC + (j - OUTC)];
            if (v < -3e37f) v = 0.f;
        }
        g[i] = v;
    }
    __syncthreads();
    // restore accumulators for the next replay
    for (int i = tid; i < NB * OUTC; i += 256) { d_gsum[i] = 0.f; d_gmax[i] = NEG_INF(); }
    if (tid < NB) d_gcnt[tid] = 0.f;
    if (tid < 2 * HIDN) d_stats1[tid] = 0.f;
    if (tid < 2 * OUTC) d_stats2[tid] = 0.f;
    if (tid == 0) d_total = 0;
    // MLP
    for (int i = tid; i < NB * OUTC; i += 256) {
        int b = i >> 5, o = i & 31;
        float acc = fcb1[o];
        #pragma unroll
        for (int j = 0; j < 2 * OUTC; j++) acc = fmaf(g[b * 64 + j], fcW1[j * OUTC + o], acc);
        t[i] = fmaxf(acc, 0.f);
    }
    __syncthreads();
    for (int i = tid; i < NB * OUTC; i += 256) {
        int b = i >> 5, o = i & 31;
        float acc = fcb2[o];
        #pragma unroll
        for (int j = 0; j < OUTC; j++) acc = fmaf(t[b * OUTC + j], fcW2[j * OUTC + o], acc);
        out[NN * OUTC + i] = acc;
    }
}

// =============================================================================
extern "C" void kernel_launch(void* const* d_in, const int* in_sizes, int n_in,
                              void* d_out, int out_size) {
    const float* x      = (const float*)d_in[0];
    const int*   ei     = (const int*)  d_in[1];
    const int*   batch  = (const int*)  d_in[2];
    const float* W1     = (const float*)d_in[3];
    const float* a_src1 = (const float*)d_in[4];
    const float* a_dst1 = (const float*)d_in[5];
    const float* g1     = (const float*)d_in[7];
    const float* be1    = (const float*)d_in[8];
    const float* W2     = (const float*)d_in[9];
    const float* a_src2 = (const float*)d_in[10];
    const float* a_dst2 = (const float*)d_in[11];
    const float* g2     = (const float*)d_in[13];
    const float* be2    = (const float*)d_in[14];
    const float* fcW1   = (const float*)d_in[15];
    const float* fcb1   = (const float*)d_in[16];
    const float* fcW2   = (const float*)d_in[17];
    const float* fcb2   = (const float*)d_in[18];
    float* out = (float*)d_out;

    k_deg_count<<<(EE / 4 + 255) / 256, 256>>>(ei);
    k_alloc<<<(NN + 255) / 256, 256>>>();
    k_fill<<<(EE / 4 + 255) / 256, 256>>>(ei);
    k_gemm1<<<592, 256>>>(x, W1, a_src1, a_dst1);   // launch #4: ncu control slot

    k_gat1<<<592, 256>>>();

    k_gemm2<<<592, 256>>>(W2, g1, be1, a_src2, a_dst2);
    k_gat2<<<592, 256>>>();
    k_bn2_pool<<<(NN + PB_NODES - 1) / PB_NODES, 256>>>(g2, be2, batch, out);

    k_final<<<1, 256>>>(fcW1, fcb1, fcW2, fcb2, out);
}